// round 15
// baseline (speedup 1.0000x reference)
#include <cuda_runtime.h>
#include <cstdint>

// DownscaleLabel: label [8,1024,1024] int32 in {-1,0..6} -> out [8,1,64,64] f32.
// Per 16x16 tile: 8-class histogram (ignore -1 -> class 7 via &7), first-max
// argmax, -1 if argmax==7 or max_count < 192 (== ratio < 0.75, exact).
//
// R15: Blackwell 256-bit loads (ld.global.nc.v8.b32) — halves LDG instruction
// and L1tex wavefront count vs the 128-bit path at identical bytes/thread.
// 1 warp = 4 horizontally-adjacent tiles, 8 lanes/tile:
//   tile = lane>>3, sub = lane&7, half = sub&1 (which 32B of the 64B tile
//   row), rg = sub>>1 (0..3) -> rows rg*4 .. rg*4+3.
// Each thread: 4 x 32B loads (32 px, 32 data regs co-live, MLP=4 of 256-bit).
// Histogram: one nibble phase per load (8 px, max 8/field) widened into byte
// accs e=(c0,c2,c4,c6), o=(c1,c3,c5,c7), max 32/byte. Reduce over 8 sub-lanes:
// xor1, xor2 in bytes (max 128), widen to 16-bit fields, xor4 (max 256).

static constexpr int SCALE = 16;
static constexpr int TILES_PER_IMG = 64 * 64;            // 4096
static constexpr int WARPS_PER_IMG = TILES_PER_IMG / 4;  // 1024

__device__ __forceinline__ void ldg256(const void* p,
                                       unsigned& r0, unsigned& r1,
                                       unsigned& r2, unsigned& r3,
                                       unsigned& r4, unsigned& r5,
                                       unsigned& r6, unsigned& r7) {
    asm volatile(
        "ld.global.nc.v8.b32 {%0,%1,%2,%3,%4,%5,%6,%7}, [%8];"
        : "=r"(r0), "=r"(r1), "=r"(r2), "=r"(r3),
          "=r"(r4), "=r"(r5), "=r"(r6), "=r"(r7)
        : "l"(p));
}

__global__ void __launch_bounds__(256, 4)
downscale_label_kernel(const int* __restrict__ label,
                       float* __restrict__ out,
                       int n_warps) {
    const int wg   = (blockIdx.x * blockDim.x + threadIdx.x) >> 5;
    const int lane = threadIdx.x & 31;
    if (wg >= n_warps) return;

    const int b   = wg >> 10;                   // / WARPS_PER_IMG (1024)
    const int wi  = wg & (WARPS_PER_IMG - 1);
    const int th  = wi >> 4;                    // tile row (64), 16 warps/row
    const int twg = wi & 15;                    // group of 4 tiles

    const int tile = lane >> 3;                 // 0..3
    const int sub  = lane & 7;
    const int half = sub & 1;                   // which 32B of 64B tile row
    const int rg   = sub >> 1;                  // row group 0..3 (4 rows)

    // Byte address: image row = 4096B. Tile col = (twg*4+tile)*64B.
    const char* base = reinterpret_cast<const char*>(label)
                       + ((size_t)b << 22)                   // b * 4MB
                       + ((size_t)(th * 16 + rg * 4) << 12)  // row * 4KB
                       + ((twg << 8) + (tile << 6) + (half << 5));

    // 4 front-batched 256-bit loads (rows rg*4 .. +3), 32 data regs.
    unsigned a0, a1, a2, a3, a4, a5, a6, a7;
    unsigned b0, b1, b2, b3, b4, b5, b6, b7;
    unsigned c0, c1, c2, c3, c4, c5, c6, c7;
    unsigned d0, d1, d2, d3, d4, d5, d6, d7;
    ldg256(base,          a0, a1, a2, a3, a4, a5, a6, a7);
    ldg256(base + 4096,   b0, b1, b2, b3, b4, b5, b6, b7);
    ldg256(base + 8192,   c0, c1, c2, c3, c4, c5, c6, c7);
    ldg256(base + 12288,  d0, d1, d2, d3, d4, d5, d6, d7);

    // Byte histograms: e = classes (0,2,4,6), o = (1,3,5,7). Max 32/byte.
    unsigned e = 0u, o = 0u;

#define HPHASE8(x0, x1, x2, x3, x4, x5, x6, x7)                 \
    {                                                           \
        unsigned n = 0u;                                        \
        n += 1u << (((x0) & 7u) << 2);                          \
        n += 1u << (((x1) & 7u) << 2);                          \
        n += 1u << (((x2) & 7u) << 2);                          \
        n += 1u << (((x3) & 7u) << 2);                          \
        n += 1u << (((x4) & 7u) << 2);                          \
        n += 1u << (((x5) & 7u) << 2);                          \
        n += 1u << (((x6) & 7u) << 2);                          \
        n += 1u << (((x7) & 7u) << 2);                          \
        e += n & 0x0F0F0F0Fu;                                   \
        o += (n >> 4) & 0x0F0F0F0Fu;                            \
    }

    HPHASE8(a0, a1, a2, a3, a4, a5, a6, a7)
    HPHASE8(b0, b1, b2, b3, b4, b5, b6, b7)
    HPHASE8(c0, c1, c2, c3, c4, c5, c6, c7)
    HPHASE8(d0, d1, d2, d3, d4, d5, d6, d7)
#undef HPHASE8

    // Reduce over the 8 sub-lanes of each tile (bytes safe to 128).
    e += __shfl_xor_sync(0xffffffffu, e, 1);   // max 64
    o += __shfl_xor_sync(0xffffffffu, o, 1);
    e += __shfl_xor_sync(0xffffffffu, e, 2);   // max 128
    o += __shfl_xor_sync(0xffffffffu, o, 2);
    // Widen byte fields -> 16-bit fields for the final (max 256) round.
    unsigned e_lo = e & 0x00FF00FFu;           // [c0 | c4<<16]
    unsigned e_hi = (e >> 8) & 0x00FF00FFu;    // [c2 | c6<<16]
    unsigned o_lo = o & 0x00FF00FFu;           // [c1 | c5<<16]
    unsigned o_hi = (o >> 8) & 0x00FF00FFu;    // [c3 | c7<<16]
    e_lo += __shfl_xor_sync(0xffffffffu, e_lo, 4);
    e_hi += __shfl_xor_sync(0xffffffffu, e_hi, 4);
    o_lo += __shfl_xor_sync(0xffffffffu, o_lo, 4);
    o_hi += __shfl_xor_sync(0xffffffffu, o_hi, 4);

    if (sub == 0) {
        int counts[8];
        counts[0] = e_lo & 0xFFFF;  counts[4] = e_lo >> 16;
        counts[2] = e_hi & 0xFFFF;  counts[6] = e_hi >> 16;
        counts[1] = o_lo & 0xFFFF;  counts[5] = o_lo >> 16;
        counts[3] = o_hi & 0xFFFF;  counts[7] = o_hi >> 16;

        int best = counts[0], arg = 0;
#pragma unroll
        for (int i = 1; i < 8; ++i) {
            if (counts[i] > best) { best = counts[i]; arg = i; }  // first-max
        }
        // ratio < 0.75  <=>  count < 192 (0.75 * 256 == 192 exactly)
        const int res = (arg == 7 || best < 192) ? -1 : arg;

        const int tw = (twg << 2) + tile;
        out[b * TILES_PER_IMG + th * 64 + tw] = (float)res;
    }
}

extern "C" void kernel_launch(void* const* d_in, const int* in_sizes, int n_in,
                              void* d_out, int out_size) {
    const int* label = (const int*)d_in[0];
    float* out = (float*)d_out;

    // 8M px / 256 px per tile / 4 tiles per warp = 8192 warps.
    const int n_tiles = in_sizes[0] / (SCALE * SCALE);
    const int n_warps = n_tiles / 4;

    const int threads = 256;                 // 8 warps/block -> 1024 blocks
    const int blocks = (n_warps * 32 + threads - 1) / threads;

    downscale_label_kernel<<<blocks, threads>>>(label, out, n_warps);
}

// round 16
// speedup vs baseline: 1.0504x; 1.0504x over previous
#include <cuda_runtime.h>
#include <cstdint>

// DownscaleLabel: label [8,1024,1024] int32 in {-1,0..6} -> out [8,1,64,64] f32.
// Per 16x16 tile: 8-class histogram (ignore -1 -> class 7 via &7), first-max
// argmax, -1 if argmax==7 or max_count < 192 (== ratio < 0.75, exact).
//
// R16 = R14 shape (fastest measured: 8 tiles/warp, 256B/thread, 128-thr
// blocks) + R15 load width (Blackwell 256-bit ld.global.nc.v8.b32): 8 loads
// instead of 16 at identical footprint -> half the LDG instructions and
// L1tex wavefronts of R14. Lane l: tile = l>>2, sub = l&3, half = sub&1
// (which 32B of the 64B tile row), rh = sub>>1 (rows 0-7 vs 8-15).
// Histogram: one nibble phase per load (8 px, max 8/field), widened into
// byte accs e=(c0,c2,c4,c6), o=(c1,c3,c5,c7), max 64/byte. Reduce over the
// 4 sub-lanes: xor1 in bytes (max 128), widen to 16-bit fields, xor2
// (max 256). Lanes sub==0 emit 8 tiles in parallel.

static constexpr int SCALE = 16;
static constexpr int TILES_PER_IMG = 64 * 64;            // 4096
static constexpr int WARPS_PER_IMG = TILES_PER_IMG / 8;  // 512

__device__ __forceinline__ void ldg256(const void* p,
                                       unsigned& r0, unsigned& r1,
                                       unsigned& r2, unsigned& r3,
                                       unsigned& r4, unsigned& r5,
                                       unsigned& r6, unsigned& r7) {
    asm volatile(
        "ld.global.nc.v8.b32 {%0,%1,%2,%3,%4,%5,%6,%7}, [%8];"
        : "=r"(r0), "=r"(r1), "=r"(r2), "=r"(r3),
          "=r"(r4), "=r"(r5), "=r"(r6), "=r"(r7)
        : "l"(p));
}

__global__ void __launch_bounds__(128, 4)
downscale_label_kernel(const int* __restrict__ label,
                       float* __restrict__ out,
                       int n_warps) {
    const int wg   = (blockIdx.x * blockDim.x + threadIdx.x) >> 5;
    const int lane = threadIdx.x & 31;
    if (wg >= n_warps) return;

    const int b   = wg >> 9;                    // / WARPS_PER_IMG (512)
    const int wi  = wg & (WARPS_PER_IMG - 1);
    const int th  = wi >> 3;                    // tile row (64), 8 warps/row
    const int twg = wi & 7;                     // group of 8 tiles

    const int tile = lane >> 2;                 // 0..7
    const int sub  = lane & 3;
    const int half = sub & 1;                   // which 32B of 64B tile row
    const int rh   = sub >> 1;                  // 0: rows 0-7, 1: rows 8-15

    // Byte address: image row = 4096B. Warp covers 512B cols x 16 rows.
    const char* base = reinterpret_cast<const char*>(label)
                       + ((size_t)b << 22)                    // b * 4MB
                       + ((size_t)(th * 16 + rh * 8) << 12)   // row * 4KB
                       + ((twg << 9) + (tile << 6) + (half << 5));

    // 8 front-batched 256-bit loads (rows rh*8 .. +7), 64 data regs.
    unsigned a0, a1, a2, a3, a4, a5, a6, a7;
    unsigned b0, b1, b2, b3, b4, b5, b6, b7;
    unsigned c0, c1, c2, c3, c4, c5, c6, c7;
    unsigned d0, d1, d2, d3, d4, d5, d6, d7;
    unsigned f0, f1, f2, f3, f4, f5, f6, f7;
    unsigned g0, g1, g2, g3, g4, g5, g6, g7;
    unsigned h0, h1, h2, h3, h4, h5, h6, h7;
    unsigned i0, i1, i2, i3, i4, i5, i6, i7;
    ldg256(base + 0 * 4096, a0, a1, a2, a3, a4, a5, a6, a7);
    ldg256(base + 1 * 4096, b0, b1, b2, b3, b4, b5, b6, b7);
    ldg256(base + 2 * 4096, c0, c1, c2, c3, c4, c5, c6, c7);
    ldg256(base + 3 * 4096, d0, d1, d2, d3, d4, d5, d6, d7);
    ldg256(base + 4 * 4096, f0, f1, f2, f3, f4, f5, f6, f7);
    ldg256(base + 5 * 4096, g0, g1, g2, g3, g4, g5, g6, g7);
    ldg256(base + 6 * 4096, h0, h1, h2, h3, h4, h5, h6, h7);
    ldg256(base + 7 * 4096, i0, i1, i2, i3, i4, i5, i6, i7);

    // Byte histograms: e = classes (0,2,4,6), o = (1,3,5,7). Max 64/byte.
    unsigned e = 0u, o = 0u;

#define HPHASE8(x0, x1, x2, x3, x4, x5, x6, x7)                 \
    {                                                           \
        unsigned n = 0u;                                        \
        n += 1u << (((x0) & 7u) << 2);                          \
        n += 1u << (((x1) & 7u) << 2);                          \
        n += 1u << (((x2) & 7u) << 2);                          \
        n += 1u << (((x3) & 7u) << 2);                          \
        n += 1u << (((x4) & 7u) << 2);                          \
        n += 1u << (((x5) & 7u) << 2);                          \
        n += 1u << (((x6) & 7u) << 2);                          \
        n += 1u << (((x7) & 7u) << 2);                          \
        e += n & 0x0F0F0F0Fu;                                   \
        o += (n >> 4) & 0x0F0F0F0Fu;                            \
    }

    HPHASE8(a0, a1, a2, a3, a4, a5, a6, a7)
    HPHASE8(b0, b1, b2, b3, b4, b5, b6, b7)
    HPHASE8(c0, c1, c2, c3, c4, c5, c6, c7)
    HPHASE8(d0, d1, d2, d3, d4, d5, d6, d7)
    HPHASE8(f0, f1, f2, f3, f4, f5, f6, f7)
    HPHASE8(g0, g1, g2, g3, g4, g5, g6, g7)
    HPHASE8(h0, h1, h2, h3, h4, h5, h6, h7)
    HPHASE8(i0, i1, i2, i3, i4, i5, i6, i7)
#undef HPHASE8

    // Reduce over the 4 sub-lanes of each tile.
    e += __shfl_xor_sync(0xffffffffu, e, 1);   // max 128, bytes still safe
    o += __shfl_xor_sync(0xffffffffu, o, 1);
    // Widen byte fields -> 16-bit fields for the final (max 256) round.
    unsigned e_lo = e & 0x00FF00FFu;           // [c0 | c4<<16]
    unsigned e_hi = (e >> 8) & 0x00FF00FFu;    // [c2 | c6<<16]
    unsigned o_lo = o & 0x00FF00FFu;           // [c1 | c5<<16]
    unsigned o_hi = (o >> 8) & 0x00FF00FFu;    // [c3 | c7<<16]
    e_lo += __shfl_xor_sync(0xffffffffu, e_lo, 2);
    e_hi += __shfl_xor_sync(0xffffffffu, e_hi, 2);
    o_lo += __shfl_xor_sync(0xffffffffu, o_lo, 2);
    o_hi += __shfl_xor_sync(0xffffffffu, o_hi, 2);

    if (sub == 0) {
        int counts[8];
        counts[0] = e_lo & 0xFFFF;  counts[4] = e_lo >> 16;
        counts[2] = e_hi & 0xFFFF;  counts[6] = e_hi >> 16;
        counts[1] = o_lo & 0xFFFF;  counts[5] = o_lo >> 16;
        counts[3] = o_hi & 0xFFFF;  counts[7] = o_hi >> 16;

        int best = counts[0], arg = 0;
#pragma unroll
        for (int i = 1; i < 8; ++i) {
            if (counts[i] > best) { best = counts[i]; arg = i; }  // first-max
        }
        // ratio < 0.75  <=>  count < 192 (0.75 * 256 == 192 exactly)
        const int res = (arg == 7 || best < 192) ? -1 : arg;

        const int tw = (twg << 3) + tile;
        out[b * TILES_PER_IMG + th * 64 + tw] = (float)res;
    }
}

extern "C" void kernel_launch(void* const* d_in, const int* in_sizes, int n_in,
                              void* d_out, int out_size) {
    const int* label = (const int*)d_in[0];
    float* out = (float*)d_out;

    // 8M px / 256 px per tile / 8 tiles per warp = 4096 warps.
    const int n_tiles = in_sizes[0] / (SCALE * SCALE);
    const int n_warps = n_tiles / 8;

    const int threads = 128;                 // 4 warps/block -> 1024 blocks
    const int blocks = (n_warps * 32 + threads - 1) / threads;

    downscale_label_kernel<<<blocks, threads>>>(label, out, n_warps);
}